// round 13
// baseline (speedup 1.0000x reference)
#include <cuda_runtime.h>

#define EPSV 1e-8f

// scratch: cs[b][r][n] = relu(cosine), 4 MB (stays in L2 between kernels)
__device__ __align__(16) float g_cs[512 * 256 * 8];

// ---------------------------------------------------------------------------
// cs kernel: 64b x 32r tile per block, one n per block. Grid (8, 8, 8) = 512.
// 256 threads (16x16), 4x2 register blocking, interleaved sub-rows
// ({ty,+16,+32,+48} x {tx,+16}). Full K=128 staged once (50.7 KB smem),
// single sync pair. Row norms: 96 threads, one private row each, no shuffles.
// ---------------------------------------------------------------------------
__global__ __launch_bounds__(256) void cs_kernel(const float* __restrict__ q,
                                                 const float* __restrict__ w)
{
    __shared__ float4 qs[64][33];     // 64 rows x 32 float4 (+1 pad) = 33.8 KB
    __shared__ float4 ws[32][33];     // 32 rows x 32 float4 (+1 pad) = 16.9 KB
    __shared__ float inv_qn_s[64];
    __shared__ float inv_wn_s[32];

    const int tid = threadIdx.x;
    const int tx = tid & 15, ty = tid >> 4;
    const int b0 = blockIdx.x * 64;
    const int r0 = blockIdx.y * 32;
    const int n  = blockIdx.z;

    const float4* q4 = (const float4*)q;
    const float4* w4 = (const float4*)w;

    // ---- stage full 64x128 q tile and 32x128 w tile (coalesced float4) ----
#pragma unroll
    for (int k = 0; k < 8; k++) {
        int idx = tid + 256 * k;
        int row = idx >> 5, col = idx & 31;
        qs[row][col] = q4[(size_t)(b0 + row) * 256 + n * 32 + col];
    }
#pragma unroll
    for (int k = 0; k < 4; k++) {
        int idx = tid + 256 * k;
        int row = idx >> 5, col = idx & 31;
        ws[row][col] = w4[(size_t)(r0 + row) * 256 + n * 32 + col];
    }
    __syncthreads();

    // ---- row norms: threads 0..63 -> q rows, 64..95 -> w rows ----
    if (tid < 96) {
        const float4* src = (tid < 64) ? &qs[tid][0] : &ws[tid - 64][0];
        float s = 0.f;
#pragma unroll
        for (int j = 0; j < 32; j++) {
            float4 v = src[j];
            s = fmaf(v.x, v.x, fmaf(v.y, v.y, fmaf(v.z, v.z, fmaf(v.w, v.w, s))));
        }
        float inv = 1.0f / fmaxf(sqrtf(s), EPSV);
        if (tid < 64) inv_qn_s[tid] = inv;
        else          inv_wn_s[tid - 64] = inv;
    }

    // ---- 4x2 register-blocked dot over K=128 ----
    float acc[4][2];
#pragma unroll
    for (int i = 0; i < 4; i++) { acc[i][0] = 0.f; acc[i][1] = 0.f; }

#pragma unroll
    for (int k = 0; k < 32; k++) {
        float4 qv[4], wv[2];
#pragma unroll
        for (int i = 0; i < 4; i++) qv[i] = qs[ty + 16 * i][k];
        wv[0] = ws[tx][k];
        wv[1] = ws[tx + 16][k];
#pragma unroll
        for (int i = 0; i < 4; i++)
#pragma unroll
            for (int j = 0; j < 2; j++) {
                acc[i][j] = fmaf(qv[i].x, wv[j].x,
                            fmaf(qv[i].y, wv[j].y,
                            fmaf(qv[i].z, wv[j].z,
                            fmaf(qv[i].w, wv[j].w, acc[i][j]))));
            }
    }
    __syncthreads();   // norms written (cheap; also guards smem reuse next launch)

    // ---- scale + relu + store ----
    float iq[4];
#pragma unroll
    for (int i = 0; i < 4; i++) iq[i] = inv_qn_s[ty + 16 * i];
    float iw0 = inv_wn_s[tx];
    float iw1 = inv_wn_s[tx + 16];

#pragma unroll
    for (int i = 0; i < 4; i++) {
        size_t rowbase = ((size_t)(b0 + ty + 16 * i) * 256 + r0 + tx) * 8 + n;
        g_cs[rowbase]          = fmaxf(acc[i][0] * iq[i] * iw0, 0.f);
        g_cs[rowbase + 16 * 8] = fmaxf(acc[i][1] * iq[i] * iw1, 0.f);
    }
}

// ---------------------------------------------------------------------------
// expand kernel (unchanged, proven): 1024 blocks x 256 threads.
// Output mapping per pair: i = s*128 + lane*4 + m -> fully contiguous STG.128.
// ---------------------------------------------------------------------------
__global__ __launch_bounds__(256) void expand_kernel(float* __restrict__ out)
{
    __shared__ float s_cs[128 * 8];

    const int tid  = threadIdx.x;
    const int warp = tid >> 5;
    const int lane = tid & 31;
    const size_t p0 = (size_t)blockIdx.x * 128;

    ((float4*)s_cs)[tid] = ((const float4*)(g_cs + p0 * 8))[tid];
    __syncthreads();

    const int t2 = (lane >> 0) & 1, t3 = (lane >> 1) & 1, t4 = (lane >> 2) & 1;
    const int t5 = (lane >> 3) & 1, t6 = (lane >> 4) & 1;

    float* outw = out + (p0 + warp * 16) * 256 + lane * 4;

#pragma unroll 4
    for (int j = 0; j < 16; j++) {
        const float* c = &s_cs[(warp * 16 + j) * 8];
        float4 cA = ((const float4*)c)[0];
        float4 cB = ((const float4*)c)[1];

        float cs0 = cA.x, cs1 = cA.y, cs2 = cA.z, cs3 = cA.w;
        float cs4 = cB.x, cs5 = cB.y, cs6 = cB.z, cs7 = cB.w;
        float ms0 = 1.f - cs0, ms1 = 1.f - cs1, ms7 = 1.f - cs7;

        float base = (t2 ? 1.f - cs2 : cs2);
        base *= (t3 ? 1.f - cs3 : cs3);
        base *= (t4 ? 1.f - cs4 : cs4);
        base *= (t5 ? 1.f - cs5 : cs5);
        base *= (t6 ? 1.f - cs6 : cs6);

        float q0 = cs0 * cs1, q1 = ms0 * cs1, q2 = cs0 * ms1, q3 = ms0 * ms1;
        float b7c = base * cs7, b7m = base * ms7;

        float4 o0, o1;
        o0.x = b7c * q0;  o0.y = b7c * q1;  o0.z = b7c * q2;  o0.w = b7c * q3;
        o1.x = b7m * q0;  o1.y = b7m * q1;  o1.z = b7m * q2;  o1.w = b7m * q3;

        float* dst = outw + (size_t)j * 256;
        __stcs((float4*)dst, o0);
        __stcs((float4*)(dst + 128), o1);
    }
}

extern "C" void kernel_launch(void* const* d_in, const int* in_sizes, int n_in,
                              void* d_out, int out_size) {
    const float* q = (const float*)d_in[0];   // 512 x 1024
    const float* w = (const float*)d_in[1];   // 256 x 1024
    float* out = (float*)d_out;               // 512 x 256 x 256

    cs_kernel<<<dim3(8, 8, 8), 256>>>(q, w);
    expand_kernel<<<1024, 256>>>(out);
}